// round 15
// baseline (speedup 1.0000x reference)
#include <cuda_runtime.h>

#define NTHREADS 256
#define TS 1028                  // tile row stride
#define ROWS 16

// smem (floats): tile 16*1028 = 16448 | 8 warp slabs * 4096 (w1 2048 + w2 2048)
#define SM_SLAB 16448
#define SM_TOTAL (SM_SLAB + 8 * 4096)   // 49216 floats = 196864 B

typedef unsigned long long u64;
typedef unsigned int u32;

// fragment-packed bf16 split weights: [layer*32+block][cell 16][lane 32] -> {h0,h1,l0,l1}
__device__ uint4 g_w1[2 * 32 * 16 * 32];
__device__ uint4 g_w2[2 * 32 * 16 * 32];

__device__ __forceinline__ u64 pack2(float lo, float hi) {
    u64 r; asm("mov.b64 %0, {%1, %2};" : "=l"(r) : "f"(lo), "f"(hi)); return r;
}
__device__ __forceinline__ void unpack2(u64 v, float& lo, float& hi) {
    asm("mov.b64 {%0, %1}, %2;" : "=f"(lo), "=f"(hi) : "l"(v));
}
__device__ __forceinline__ u32 bpack(float lo, float hi) {
    u32 r; asm("cvt.rn.bf16x2.f32 %0, %1, %2;" : "=r"(r) : "f"(hi), "f"(lo)); return r;
}
__device__ __forceinline__ float blof(u32 w) { return __uint_as_float(w << 16); }
__device__ __forceinline__ float bhif(u32 w) { return __uint_as_float(w & 0xFFFF0000u); }
__device__ __forceinline__ void bsplit2(float x0, float x1, u32& h, u32& l) {
    h = bpack(x0, x1);
    l = bpack(x0 - blof(h), x1 - bhif(h));
}
__device__ __forceinline__ u32 s2u(const void* p) {
    u32 r;
    asm("{.reg .u64 t; cvta.to.shared.u64 t, %1; cvt.u32.u64 %0, t;}" : "=r"(r) : "l"(p));
    return r;
}
__device__ __forceinline__ void cpa16(u32 dst, const void* src) {
    asm volatile("cp.async.cg.shared.global [%0], [%1], 16;" :: "r"(dst), "l"(src));
}
__device__ __forceinline__ void mma16(float* c, const u32* a, u32 b0, u32 b1) {
    asm volatile(
        "mma.sync.aligned.m16n8k16.row.col.f32.bf16.bf16.f32 "
        "{%0,%1,%2,%3}, {%4,%5,%6,%7}, {%8,%9}, {%0,%1,%2,%3};"
        : "+f"(c[0]), "+f"(c[1]), "+f"(c[2]), "+f"(c[3])
        : "r"(a[0]), "r"(a[1]), "r"(a[2]), "r"(a[3]), "r"(b0), "r"(b1));
}
__device__ __forceinline__ float elu(float v) {
    return v > 0.f ? v : (__expf(v) - 1.f);
}

// ---- prep: split weights into bf16 hi/lo, fragment-packed uint4 cells ----
__global__ void prep_kernel(
    const float* __restrict__ W1a, const float* __restrict__ W2a,
    const float* __restrict__ W1b, const float* __restrict__ W2b)
{
    int id = blockIdx.x * blockDim.x + threadIdx.x;   // 65536 total
    int lane = id & 31;
    int cell = (id >> 5) & 15;
    int b    = (id >> 9) & 31;
    int mat  = (id >> 14) & 1;
    int l    = (id >> 15) & 1;
    int g = lane >> 2, t4 = lane & 3;

    float f00, f01, f10, f11;
    if (mat == 0) {
        int nt = cell >> 1, kt = cell & 1;
        int k0 = kt * 16 + 2 * t4, n = nt * 8 + g;
        const float* W = (l ? W1b : W1a) + b * 2048;
        f00 = W[k0 * 64 + n];       f01 = W[(k0 + 1) * 64 + n];
        f10 = W[(k0 + 8) * 64 + n]; f11 = W[(k0 + 9) * 64 + n];
    } else {
        int nt = cell >> 2, kt = cell & 3;
        int k0 = kt * 16 + 2 * t4, n = nt * 8 + g;
        const float* W = (l ? W2b : W2a) + b * 2048;
        f00 = W[k0 * 32 + n];       f01 = W[(k0 + 1) * 32 + n];
        f10 = W[(k0 + 8) * 32 + n]; f11 = W[(k0 + 9) * 32 + n];
    }
    u32 h0, l0, h1, l1;
    bsplit2(f00, f01, h0, l0);
    bsplit2(f10, f11, h1, l1);
    uint4 v; v.x = h0; v.y = h1; v.z = l0; v.w = l1;
    uint4* dst = mat ? g_w2 : g_w1;
    dst[((l * 32 + b) * 16 + cell) * 32 + lane] = v;
}

// in-place per-row 32x32 block transpose; 8 warps x 2 rows
__device__ __forceinline__ void transpose_tile(float* tile, int warp, int lane) {
    const int a2 = lane >> 3;
    const int B  = lane & 7;
    #pragma unroll
    for (int rr = 0; rr < 2; ++rr) {
        float* row = tile + (warp * 2 + rr) * TS;
        float4 v[2][4];
        #pragma unroll
        for (int h = 0; h < 2; ++h) {
            int A = a2 + 4 * h;
            #pragma unroll
            for (int i = 0; i < 4; ++i)
                v[h][i] = *(const float4*)(row + 32 * (4 * A + i) + 4 * B);
        }
        __syncwarp();
        #pragma unroll
        for (int h = 0; h < 2; ++h) {
            int A = a2 + 4 * h;
            #pragma unroll
            for (int i = 0; i < 4; ++i) {
                float4 t;
                t.x = ((const float*)&v[h][0])[i];
                t.y = ((const float*)&v[h][1])[i];
                t.z = ((const float*)&v[h][2])[i];
                t.w = ((const float*)&v[h][3])[i];
                *(float4*)(row + 32 * (4 * B + i) + 4 * A) = t;
            }
        }
        __syncwarp();
    }
}

__global__ __launch_bounds__(NTHREADS, 1) void mixer_kernel(
    const float* __restrict__ x,
    const float* __restrict__ B1a, const float* __restrict__ B2a,
    const float* __restrict__ B1b, const float* __restrict__ B2b,
    float* __restrict__ out)
{
    extern __shared__ float smem[];
    float* tile = smem;

    const int tid  = threadIdx.x;
    const int warp = tid >> 5;
    const int lane = tid & 31;
    const int g    = lane >> 2;
    const int t4   = lane & 3;
    const long row0 = (long)blockIdx.x * ROWS;

    const float* B1p[2] = {B1a, B1b};
    const float* B2p[2] = {B2a, B2b};

    // per-warp weight slab: w1 frags at +0 (2048 floats), w2 frags at +2048
    float* slab = smem + SM_SLAB + warp * 4096;
    const u32 slab1_u = s2u(slab);
    const u32 slab2_u = slab1_u + 8192u;
    const uint4* s1q = (const uint4*)slab + lane;
    const uint4* s2q = (const uint4*)(slab + 2048) + lane;

    // issue cp.async for stage si's w1 / w2 into this warp's slab (one group each)
    auto fetch_w1 = [&](int si) {
        const int lb = (si >> 2) * 32 + (si & 3) * 8 + warp;
        const uint4* src = g_w1 + (size_t)lb * 512 + lane;
        #pragma unroll
        for (int c = 0; c < 16; ++c)
            cpa16(slab1_u + (u32)(c * 32 + lane) * 16u, src + c * 32);
        asm volatile("cp.async.commit_group;");
    };
    auto fetch_w2 = [&](int si) {
        const int lb = (si >> 2) * 32 + (si & 3) * 8 + warp;
        const uint4* src = g_w2 + (size_t)lb * 512 + lane;
        #pragma unroll
        for (int c = 0; c < 16; ++c)
            cpa16(slab2_u + (u32)(c * 32 + lane) * 16u, src + c * 32);
        asm volatile("cp.async.commit_group;");
    };

    fetch_w1(0);          // group: w1[0]
    fetch_w2(0);          // group: w2[0]

    // ---- load x tile (overlaps the weight prefetch) ----
    {
        const float4* src = (const float4*)(x + row0 * 1024);
        #pragma unroll
        for (int it = 0; it < 16; ++it) {
            int i = tid + it * NTHREADS;
            int r = i >> 8, c4 = i & 255;
            *(float4*)(tile + r * TS + c4 * 4) = src[r * 256 + c4];
        }
    }
    __syncthreads();

    #pragma unroll 1
    for (int si = 0; si < 8; ++si) {
        if (si == 4) {                       // layer boundary
            __syncthreads();
            transpose_tile(tile, warp, lane);
            __syncthreads();
        }
        const int layer = si >> 2;
        const int blk   = (si & 3) * 8 + warp;
        const int cbase = blk * 32;

        // ---- A-fragments: bf16 split of x, rows {g, g+8} (before weight wait) ----
        u32 xh[2][4], xl[2][4];
        {
            const float* xr = tile + g * TS + cbase;
            #pragma unroll
            for (int kc = 0; kc < 2; ++kc) {
                int c0 = kc * 16 + 2 * t4;
                float2 v0 = *(const float2*)(xr + c0);
                float2 v1 = *(const float2*)(xr + 8 * TS + c0);
                float2 v2 = *(const float2*)(xr + c0 + 8);
                float2 v3 = *(const float2*)(xr + 8 * TS + c0 + 8);
                bsplit2(v0.x, v0.y, xh[kc][0], xl[kc][0]);
                bsplit2(v1.x, v1.y, xh[kc][1], xl[kc][1]);
                bsplit2(v2.x, v2.y, xh[kc][2], xl[kc][2]);
                bsplit2(v3.x, v3.y, xh[kc][3], xl[kc][3]);
            }
        }

        // ---- c2 accumulators: bias + residual (also before weight wait) ----
        float c2[4][4];
        {
            const u64* b2q = (const u64*)(B2p[layer] + blk * 32);
            const float* resp = tile + g * TS + cbase;
            #pragma unroll
            for (int nt = 0; nt < 4; ++nt) {
                float blo, bhi, r0l, r0h, r1l, r1h;
                unpack2(b2q[nt * 4 + t4], blo, bhi);
                unpack2(*(const u64*)(resp + nt * 8 + 2 * t4), r0l, r0h);
                unpack2(*(const u64*)(resp + 8 * TS + nt * 8 + 2 * t4), r1l, r1h);
                c2[nt][0] = blo + r0l; c2[nt][1] = bhi + r0h;
                c2[nt][2] = blo + r1l; c2[nt][3] = bhi + r1h;
            }
        }

        // ---- wait for w1[si] (leaves w2[si] pending) ----
        asm volatile("cp.async.wait_group 1;" ::: "memory");
        __syncwarp();

        // ---- matmul1: 16 rows x 64 hidden, weights via LDS.128 ----
        float c1[8][4];
        {
            const u64* b1q = (const u64*)(B1p[layer] + blk * 64);
            #pragma unroll
            for (int nt = 0; nt < 8; ++nt) {
                float blo, bhi;
                unpack2(b1q[nt * 4 + t4], blo, bhi);
                c1[nt][0] = blo; c1[nt][1] = bhi; c1[nt][2] = blo; c1[nt][3] = bhi;
            }
        }
        #pragma unroll
        for (int nt = 0; nt < 8; ++nt) {
            uint4 B0 = s1q[(nt * 2 + 0) * 32];
            uint4 B1 = s1q[(nt * 2 + 1) * 32];
            mma16(c1[nt], xh[0], B0.x, B0.y);
            mma16(c1[nt], xl[0], B0.x, B0.y);
            mma16(c1[nt], xh[0], B0.z, B0.w);
            mma16(c1[nt], xh[1], B1.x, B1.y);
            mma16(c1[nt], xl[1], B1.x, B1.y);
            mma16(c1[nt], xh[1], B1.z, B1.w);
        }

        // ---- prefetch w1[si+1]; hides behind ELU + mm2 ----
        if (si < 7) fetch_w1(si + 1);

        // ---- ELU in registers, rebuild mm2 A-fragments directly ----
        u32 a2h[4][4], a2l[4][4];
        #pragma unroll
        for (int nt = 0; nt < 8; ++nt) {
            c1[nt][0] = elu(c1[nt][0]); c1[nt][1] = elu(c1[nt][1]);
            c1[nt][2] = elu(c1[nt][2]); c1[nt][3] = elu(c1[nt][3]);
        }
        #pragma unroll
        for (int kt = 0; kt < 4; ++kt) {
            bsplit2(c1[2*kt][0],   c1[2*kt][1],   a2h[kt][0], a2l[kt][0]);
            bsplit2(c1[2*kt][2],   c1[2*kt][3],   a2h[kt][1], a2l[kt][1]);
            bsplit2(c1[2*kt+1][0], c1[2*kt+1][1], a2h[kt][2], a2l[kt][2]);
            bsplit2(c1[2*kt+1][2], c1[2*kt+1][3], a2h[kt][3], a2l[kt][3]);
        }

        // ---- wait for w2[si] (leaves w1[si+1] pending when si<7) ----
        if (si < 7) asm volatile("cp.async.wait_group 1;" ::: "memory");
        else        asm volatile("cp.async.wait_group 0;" ::: "memory");
        __syncwarp();

        // ---- matmul2: 16 rows x 32 out, weights via LDS.128 ----
        #pragma unroll
        for (int kt = 0; kt < 4; ++kt) {
            #pragma unroll
            for (int nt = 0; nt < 4; ++nt) {
                uint4 B = s2q[(nt * 4 + kt) * 32];
                mma16(c2[nt], a2h[kt], B.x, B.y);
                mma16(c2[nt], a2l[kt], B.x, B.y);
                mma16(c2[nt], a2h[kt], B.z, B.w);
            }
        }

        // ---- prefetch w2[si+1]; hides behind next stage's frag-build + mm1 ----
        if (si < 7) fetch_w2(si + 1);

        // ---- writeback ----
        {
            float* resp = tile + g * TS + cbase;
            #pragma unroll
            for (int nt = 0; nt < 4; ++nt) {
                *(u64*)(resp + nt * 8 + 2 * t4)          = pack2(c2[nt][0], c2[nt][1]);
                *(u64*)(resp + 8 * TS + nt * 8 + 2 * t4) = pack2(c2[nt][2], c2[nt][3]);
            }
        }
    }

    __syncthreads();
    transpose_tile(tile, warp, lane);        // undo layer-1 permutation
    __syncthreads();

    // ---- store output ----
    {
        float4* dst = (float4*)(out + row0 * 1024);
        #pragma unroll
        for (int it = 0; it < 16; ++it) {
            int i = tid + it * NTHREADS;
            int r = i >> 8, c4 = i & 255;
            dst[r * 256 + c4] = *(const float4*)(tile + r * TS + c4 * 4);
        }
    }
}

extern "C" void kernel_launch(void* const* d_in, const int* in_sizes, int n_in,
                              void* d_out, int out_size) {
    const float* x   = (const float*)d_in[0];
    const float* W1a = (const float*)d_in[1];
    const float* B1a = (const float*)d_in[2];
    const float* W2a = (const float*)d_in[3];
    const float* B2a = (const float*)d_in[4];
    const float* W1b = (const float*)d_in[5];
    const float* B1b = (const float*)d_in[6];
    const float* W2b = (const float*)d_in[7];
    const float* B2b = (const float*)d_in[8];
    float* out = (float*)d_out;

    int rows = in_sizes[0] / 1024;
    int grid = rows / ROWS;                    // 1024

    size_t smem_bytes = (size_t)SM_TOTAL * sizeof(float);   // 196864 B
    static int configured = -1;
    if (configured < 0) {
        cudaFuncSetAttribute(mixer_kernel,
                             cudaFuncAttributeMaxDynamicSharedMemorySize,
                             (int)smem_bytes);
        configured = 1;
    }

    prep_kernel<<<256, 256>>>(W1a, W2a, W1b, W2b);
    mixer_kernel<<<grid, NTHREADS, smem_bytes>>>(
        x, B1a, B2a, B1b, B2b, out);
}

// round 16
// speedup vs baseline: 1.0282x; 1.0282x over previous
#include <cuda_runtime.h>

#define NTHREADS 256
#define RS 36                     // subtile row stride (floats)
#define BT (64 * RS)              // per-block subtile (2304 floats)
#define SM_TOTAL (8 * BT)         // 18432 floats = 73728 B

typedef unsigned long long u64;
typedef unsigned int u32;

__device__ float g_y0[16384 * 1024];   // 64 MB inter-layer scratch

// fragment-packed bf16 split weights: [layer*32+block][cell 16][lane 32] -> {h0,h1,l0,l1}
__device__ uint4 g_w1[2 * 32 * 16 * 32];
__device__ uint4 g_w2[2 * 32 * 16 * 32];

__device__ __forceinline__ u64 pack2(float lo, float hi) {
    u64 r; asm("mov.b64 %0, {%1, %2};" : "=l"(r) : "f"(lo), "f"(hi)); return r;
}
__device__ __forceinline__ void unpack2(u64 v, float& lo, float& hi) {
    asm("mov.b64 {%0, %1}, %2;" : "=f"(lo), "=f"(hi) : "l"(v));
}
__device__ __forceinline__ u32 bpack(float lo, float hi) {
    u32 r; asm("cvt.rn.bf16x2.f32 %0, %1, %2;" : "=r"(r) : "f"(hi), "f"(lo)); return r;
}
__device__ __forceinline__ float blof(u32 w) { return __uint_as_float(w << 16); }
__device__ __forceinline__ float bhif(u32 w) { return __uint_as_float(w & 0xFFFF0000u); }
__device__ __forceinline__ void bsplit2(float x0, float x1, u32& h, u32& l) {
    h = bpack(x0, x1);
    l = bpack(x0 - blof(h), x1 - bhif(h));
}
__device__ __forceinline__ void mma16(float* c, const u32* a, u32 b0, u32 b1) {
    asm volatile(
        "mma.sync.aligned.m16n8k16.row.col.f32.bf16.bf16.f32 "
        "{%0,%1,%2,%3}, {%4,%5,%6,%7}, {%8,%9}, {%0,%1,%2,%3};"
        : "+f"(c[0]), "+f"(c[1]), "+f"(c[2]), "+f"(c[3])
        : "r"(a[0]), "r"(a[1]), "r"(a[2]), "r"(a[3]), "r"(b0), "r"(b1));
}
__device__ __forceinline__ float elu(float v) {
    return v > 0.f ? v : (__expf(v) - 1.f);
}

// ---- prep: split weights into bf16 hi/lo, fragment-packed uint4 cells ----
__global__ void prep_kernel(
    const float* __restrict__ W1a, const float* __restrict__ W2a,
    const float* __restrict__ W1b, const float* __restrict__ W2b)
{
    int id = blockIdx.x * blockDim.x + threadIdx.x;   // 65536 total
    int lane = id & 31;
    int cell = (id >> 5) & 15;
    int b    = (id >> 9) & 31;
    int mat  = (id >> 14) & 1;
    int l    = (id >> 15) & 1;
    int g = lane >> 2, t4 = lane & 3;

    float f00, f01, f10, f11;
    if (mat == 0) {
        int nt = cell >> 1, kt = cell & 1;
        int k0 = kt * 16 + 2 * t4, n = nt * 8 + g;
        const float* W = (l ? W1b : W1a) + b * 2048;
        f00 = W[k0 * 64 + n];       f01 = W[(k0 + 1) * 64 + n];
        f10 = W[(k0 + 8) * 64 + n]; f11 = W[(k0 + 9) * 64 + n];
    } else {
        int nt = cell >> 2, kt = cell & 3;
        int k0 = kt * 16 + 2 * t4, n = nt * 8 + g;
        const float* W = (l ? W2b : W2a) + b * 2048;
        f00 = W[k0 * 32 + n];       f01 = W[(k0 + 1) * 32 + n];
        f10 = W[(k0 + 8) * 32 + n]; f11 = W[(k0 + 9) * 32 + n];
    }
    u32 h0, l0, h1, l1;
    bsplit2(f00, f01, h0, l0);
    bsplit2(f10, f11, h1, l1);
    uint4 v; v.x = h0; v.y = h1; v.z = l0; v.w = l1;
    uint4* dst = mat ? g_w2 : g_w1;
    dst[((l * 32 + b) * 16 + cell) * 32 + lane] = v;
}

// One layer. CTA = 64 rows x 8 adjacent blocks.
// layer==0: in -> g_y0 (contiguous 256-col slab per block-group)
// layer==1: g_y0 -> out (strided cols n+32k, 32B-chunk pattern)
__global__ __launch_bounds__(NTHREADS, 2) void layer_kernel(
    const float* __restrict__ in, float* __restrict__ outp,
    const float* __restrict__ B1, const float* __restrict__ B2,
    int layer)
{
    extern __shared__ float tile[];   // [8 blocks][64 rows][36]

    const int tid  = threadIdx.x;
    const int warp = tid >> 5;
    const int lane = tid & 31;
    const int g    = lane >> 2;
    const int t4   = lane & 3;
    const int m    = warp & 3;        // m-group (16 rows)
    const int bh   = warp >> 2;       // block half
    const int rt   = blockIdx.x & 255;
    const int bg   = blockIdx.x >> 8; // block group (bg-major grid -> L1 weight sharing)
    const long rowbase = (long)rt * 64;

    const float* src = (layer == 0) ? in : g_y0;
    float*       dst = (layer == 0) ? g_y0 : outp;

    // ---- load x tile into per-block subtiles ----
    if (layer == 0) {
        #pragma unroll
        for (int it = 0; it < 16; ++it) {
            int idx = tid + it * NTHREADS;           // [0, 4096)
            int r = idx >> 6, c4 = idx & 63;
            float4 v = *(const float4*)(src + (rowbase + r) * 1024 + bg * 256 + c4 * 4);
            int b = c4 >> 3, k = (c4 & 7) * 4;
            *(float4*)(tile + b * BT + r * RS + k) = v;
        }
    } else {
        #pragma unroll
        for (int it = 0; it < 16; ++it) {
            int idx = tid + it * NTHREADS;
            int r = idx >> 6, h = idx & 63;
            int k = h >> 1, half = h & 1;
            float4 v = *(const float4*)(src + (rowbase + r) * 1024 + 32 * k + 8 * bg + 4 * half);
            float* tp = tile + r * RS + k;
            tp[(4 * half + 0) * BT] = v.x;
            tp[(4 * half + 1) * BT] = v.y;
            tp[(4 * half + 2) * BT] = v.z;
            tp[(4 * half + 3) * BT] = v.w;
        }
    }
    __syncthreads();

    // ---- compute: warp = (m-group, block-half); 4 blocks sequentially ----
    #pragma unroll 1
    for (int i = 0; i < 4; ++i) {
        const int b  = bh * 4 + i;
        const int n  = 8 * bg + b;            // global block index
        const int lb = layer * 32 + n;

        const uint4* w1q = g_w1 + (size_t)lb * 512 + lane;
        const uint4* w2q = g_w2 + (size_t)lb * 512 + lane;
        float* xr = tile + b * BT + (m * 16 + g) * RS;

        // A-fragments + fp32 residual copies
        u32 xh[2][4], xl[2][4];
        float2 res[2][4];
        #pragma unroll
        for (int kc = 0; kc < 2; ++kc) {
            int c0 = kc * 16 + 2 * t4;
            res[kc][0] = *(const float2*)(xr + c0);
            res[kc][1] = *(const float2*)(xr + 8 * RS + c0);
            res[kc][2] = *(const float2*)(xr + c0 + 8);
            res[kc][3] = *(const float2*)(xr + 8 * RS + c0 + 8);
            bsplit2(res[kc][0].x, res[kc][0].y, xh[kc][0], xl[kc][0]);
            bsplit2(res[kc][1].x, res[kc][1].y, xh[kc][1], xl[kc][1]);
            bsplit2(res[kc][2].x, res[kc][2].y, xh[kc][2], xl[kc][2]);
            bsplit2(res[kc][3].x, res[kc][3].y, xh[kc][3], xl[kc][3]);
        }

        // matmul1: 16 rows x 64 hidden
        float c1[8][4];
        {
            const u64* b1q = (const u64*)(B1 + n * 64);
            #pragma unroll
            for (int nt = 0; nt < 8; ++nt) {
                float blo, bhi;
                unpack2(b1q[nt * 4 + t4], blo, bhi);
                c1[nt][0] = blo; c1[nt][1] = bhi; c1[nt][2] = blo; c1[nt][3] = bhi;
            }
        }
        #pragma unroll
        for (int nt = 0; nt < 8; ++nt) {
            uint4 B0 = w1q[(nt * 2 + 0) * 32];
            uint4 B1f = w1q[(nt * 2 + 1) * 32];
            mma16(c1[nt], xh[0], B0.x, B0.y);
            mma16(c1[nt], xl[0], B0.x, B0.y);
            mma16(c1[nt], xh[0], B0.z, B0.w);
            mma16(c1[nt], xh[1], B1f.x, B1f.y);
            mma16(c1[nt], xl[1], B1f.x, B1f.y);
            mma16(c1[nt], xh[1], B1f.z, B1f.w);
        }

        // ELU in registers, rebuild mm2 A-fragments
        u32 a2h[4][4], a2l[4][4];
        #pragma unroll
        for (int nt = 0; nt < 8; ++nt) {
            c1[nt][0] = elu(c1[nt][0]); c1[nt][1] = elu(c1[nt][1]);
            c1[nt][2] = elu(c1[nt][2]); c1[nt][3] = elu(c1[nt][3]);
        }
        #pragma unroll
        for (int kt = 0; kt < 4; ++kt) {
            bsplit2(c1[2*kt][0],   c1[2*kt][1],   a2h[kt][0], a2l[kt][0]);
            bsplit2(c1[2*kt][2],   c1[2*kt][3],   a2h[kt][1], a2l[kt][1]);
            bsplit2(c1[2*kt+1][0], c1[2*kt+1][1], a2h[kt][2], a2l[kt][2]);
            bsplit2(c1[2*kt+1][2], c1[2*kt+1][3], a2h[kt][3], a2l[kt][3]);
        }

        // matmul2: bias + residual from registers
        float c2[4][4];
        {
            const u64* b2q = (const u64*)(B2 + n * 32);
            #pragma unroll
            for (int nt = 0; nt < 4; ++nt) {
                float blo, bhi;
                unpack2(b2q[nt * 4 + t4], blo, bhi);
                const float2 rl = res[nt >> 1][(nt & 1) * 2];
                const float2 rh = res[nt >> 1][(nt & 1) * 2 + 1];
                c2[nt][0] = blo + rl.x; c2[nt][1] = bhi + rl.y;
                c2[nt][2] = blo + rh.x; c2[nt][3] = bhi + rh.y;
            }
        }
        #pragma unroll
        for (int kt = 0; kt < 4; ++kt) {
            #pragma unroll
            for (int nt = 0; nt < 4; ++nt) {
                uint4 B = w2q[(nt * 4 + kt) * 32];
                mma16(c2[nt], a2h[kt], B.x, B.y);
                mma16(c2[nt], a2l[kt], B.x, B.y);
                mma16(c2[nt], a2h[kt], B.z, B.w);
            }
        }
        // in-place writeback (unit owns these cells)
        #pragma unroll
        for (int nt = 0; nt < 4; ++nt) {
            *(u64*)(xr + nt * 8 + 2 * t4)          = pack2(c2[nt][0], c2[nt][1]);
            *(u64*)(xr + 8 * RS + nt * 8 + 2 * t4) = pack2(c2[nt][2], c2[nt][3]);
        }
    }
    __syncthreads();

    // ---- store output tile ----
    if (layer == 0) {
        #pragma unroll
        for (int it = 0; it < 16; ++it) {
            int idx = tid + it * NTHREADS;
            int r = idx >> 6, c4 = idx & 63;
            int b = c4 >> 3, k = (c4 & 7) * 4;
            float4 v = *(const float4*)(tile + b * BT + r * RS + k);
            *(float4*)(dst + (rowbase + r) * 1024 + bg * 256 + c4 * 4) = v;
        }
    } else {
        #pragma unroll
        for (int it = 0; it < 16; ++it) {
            int idx = tid + it * NTHREADS;
            int r = idx >> 6, h = idx & 63;
            int k = h >> 1, half = h & 1;
            const float* tp = tile + r * RS + k;
            float4 v;
            v.x = tp[(4 * half + 0) * BT];
            v.y = tp[(4 * half + 1) * BT];
            v.z = tp[(4 * half + 2) * BT];
            v.w = tp[(4 * half + 3) * BT];
            *(float4*)(dst + (rowbase + r) * 1024 + 32 * k + 8 * bg + 4 * half) = v;
        }
    }
}

extern "C" void kernel_launch(void* const* d_in, const int* in_sizes, int n_in,
                              void* d_out, int out_size) {
    const float* x   = (const float*)d_in[0];
    const float* W1a = (const float*)d_in[1];
    const float* B1a = (const float*)d_in[2];
    const float* W2a = (const float*)d_in[3];
    const float* B2a = (const float*)d_in[4];
    const float* W1b = (const float*)d_in[5];
    const float* B1b = (const float*)d_in[6];
    const float* W2b = (const float*)d_in[7];
    const float* B2b = (const float*)d_in[8];
    float* out = (float*)d_out;

    size_t smem_bytes = (size_t)SM_TOTAL * sizeof(float);   // 73728 B
    static int configured = -1;
    if (configured < 0) {
        cudaFuncSetAttribute(layer_kernel,
                             cudaFuncAttributeMaxDynamicSharedMemorySize,
                             (int)smem_bytes);
        configured = 1;
    }

    prep_kernel<<<256, 256>>>(W1a, W2a, W1b, W2b);
    layer_kernel<<<1024, NTHREADS, smem_bytes>>>(x, out, B1a, B2a, 0);
    layer_kernel<<<1024, NTHREADS, smem_bytes>>>(x, out, B1b, B2b, 1);
}

// round 17
// speedup vs baseline: 1.4186x; 1.3798x over previous
#include <cuda_runtime.h>

#define NTHREADS 256
#define TS 1028                  // tile row stride
#define ROWS 16

#define SM_TOTAL (16 * TS)       // 16448 floats = 65792 B

typedef unsigned long long u64;
typedef unsigned int u32;

// fragment-packed fp16 weights: [layer*32+block][cellpair 8][lane 32] -> uint4
// uint4 = {cell(2cp).r0, cell(2cp).r1, cell(2cp+1).r0, cell(2cp+1).r1}
__device__ uint4 g_w1[2 * 32 * 8 * 32];
__device__ uint4 g_w2[2 * 32 * 8 * 32];

__device__ __forceinline__ u64 pack2(float lo, float hi) {
    u64 r; asm("mov.b64 %0, {%1, %2};" : "=l"(r) : "f"(lo), "f"(hi)); return r;
}
__device__ __forceinline__ void unpack2(u64 v, float& lo, float& hi) {
    asm("mov.b64 {%0, %1}, %2;" : "=f"(lo), "=f"(hi) : "l"(v));
}
__device__ __forceinline__ u32 hpack(float lo, float hi) {
    u32 r; asm("cvt.rn.f16x2.f32 %0, %1, %2;" : "=r"(r) : "f"(hi), "f"(lo)); return r;
}
__device__ __forceinline__ void mma16(float* c, const u32* a, u32 b0, u32 b1) {
    asm volatile(
        "mma.sync.aligned.m16n8k16.row.col.f32.f16.f16.f32 "
        "{%0,%1,%2,%3}, {%4,%5,%6,%7}, {%8,%9}, {%0,%1,%2,%3};"
        : "+f"(c[0]), "+f"(c[1]), "+f"(c[2]), "+f"(c[3])
        : "r"(a[0]), "r"(a[1]), "r"(a[2]), "r"(a[3]), "r"(b0), "r"(b1));
}
__device__ __forceinline__ float elu(float v) {
    return v > 0.f ? v : (__expf(v) - 1.f);
}

// ---- prep: convert weights to fp16, fragment-packed uint4 cell-pairs ----
__global__ void prep_kernel(
    const float* __restrict__ W1a, const float* __restrict__ W2a,
    const float* __restrict__ W1b, const float* __restrict__ W2b)
{
    int id = blockIdx.x * blockDim.x + threadIdx.x;   // 65536 total
    int lane = id & 31;
    int cell = (id >> 5) & 15;
    int b    = (id >> 9) & 31;
    int mat  = (id >> 14) & 1;
    int l    = (id >> 15) & 1;
    int g = lane >> 2, t4 = lane & 3;

    float f00, f01, f10, f11;
    if (mat == 0) {
        int nt = cell >> 1, kt = cell & 1;
        int k0 = kt * 16 + 2 * t4, n = nt * 8 + g;
        const float* W = (l ? W1b : W1a) + b * 2048;
        f00 = W[k0 * 64 + n];       f01 = W[(k0 + 1) * 64 + n];
        f10 = W[(k0 + 8) * 64 + n]; f11 = W[(k0 + 9) * 64 + n];
    } else {
        int nt = cell >> 2, kt = cell & 3;
        int k0 = kt * 16 + 2 * t4, n = nt * 8 + g;
        const float* W = (l ? W2b : W2a) + b * 2048;
        f00 = W[k0 * 32 + n];       f01 = W[(k0 + 1) * 32 + n];
        f10 = W[(k0 + 8) * 32 + n]; f11 = W[(k0 + 9) * 32 + n];
    }
    u32 r0 = hpack(f00, f01);
    u32 r1 = hpack(f10, f11);
    // uint2 slot inside the uint4 cell-pair array
    int cp = cell >> 1, half = cell & 1;
    int lb = l * 32 + b;
    u32* dst = (u32*)(mat ? g_w2 : g_w1);
    int base = (((lb * 8 + cp) * 32 + lane) * 2 + half) * 2;
    dst[base]     = r0;
    dst[base + 1] = r1;
}

// in-place per-row 32x32 block transpose; 8 warps x 2 rows
__device__ __forceinline__ void transpose_tile(float* tile, int warp, int lane) {
    const int a2 = lane >> 3;
    const int B  = lane & 7;
    #pragma unroll
    for (int rr = 0; rr < 2; ++rr) {
        float* row = tile + (warp * 2 + rr) * TS;
        float4 v[2][4];
        #pragma unroll
        for (int h = 0; h < 2; ++h) {
            int A = a2 + 4 * h;
            #pragma unroll
            for (int i = 0; i < 4; ++i)
                v[h][i] = *(const float4*)(row + 32 * (4 * A + i) + 4 * B);
        }
        __syncwarp();
        #pragma unroll
        for (int h = 0; h < 2; ++h) {
            int A = a2 + 4 * h;
            #pragma unroll
            for (int i = 0; i < 4; ++i) {
                float4 t;
                t.x = ((const float*)&v[h][0])[i];
                t.y = ((const float*)&v[h][1])[i];
                t.z = ((const float*)&v[h][2])[i];
                t.w = ((const float*)&v[h][3])[i];
                *(float4*)(row + 32 * (4 * B + i) + 4 * A) = t;
            }
        }
        __syncwarp();
    }
}

__global__ __launch_bounds__(NTHREADS, 2) void mixer_kernel(
    const float* __restrict__ x,
    const float* __restrict__ B1a, const float* __restrict__ B2a,
    const float* __restrict__ B1b, const float* __restrict__ B2b,
    float* __restrict__ out)
{
    extern __shared__ float smem[];
    float* tile = smem;

    const int tid  = threadIdx.x;
    const int warp = tid >> 5;
    const int lane = tid & 31;
    const int g    = lane >> 2;
    const int t4   = lane & 3;
    const long row0 = (long)blockIdx.x * ROWS;

    const float* B1p[2] = {B1a, B1b};
    const float* B2p[2] = {B2a, B2b};

    // ---- load x tile ----
    {
        const float4* src = (const float4*)(x + row0 * 1024);
        #pragma unroll
        for (int it = 0; it < 16; ++it) {
            int i = tid + it * NTHREADS;
            int r = i >> 8, c4 = i & 255;
            *(float4*)(tile + r * TS + c4 * 4) = src[r * 256 + c4];
        }
    }
    __syncthreads();

    #pragma unroll 1
    for (int si = 0; si < 8; ++si) {
        if (si == 4) {                       // layer boundary
            __syncthreads();
            transpose_tile(tile, warp, lane);
            __syncthreads();
        }
        const int layer = si >> 2;
        const int blk   = (si & 3) * 8 + warp;
        const int lb    = layer * 32 + blk;
        const int cbase = blk * 32;

        const uint4* w1q = g_w1 + (size_t)lb * 256 + lane;
        const uint4* w2q = g_w2 + (size_t)lb * 256 + lane;

        // ---- A-fragments: fp16 pack of x, rows {g, g+8}; keep fp32 residuals ----
        u32 xa[2][4];
        float2 res[2][4];
        {
            const float* xr = tile + g * TS + cbase;
            #pragma unroll
            for (int kc = 0; kc < 2; ++kc) {
                int c0 = kc * 16 + 2 * t4;
                res[kc][0] = *(const float2*)(xr + c0);
                res[kc][1] = *(const float2*)(xr + 8 * TS + c0);
                res[kc][2] = *(const float2*)(xr + c0 + 8);
                res[kc][3] = *(const float2*)(xr + 8 * TS + c0 + 8);
                xa[kc][0] = hpack(res[kc][0].x, res[kc][0].y);
                xa[kc][1] = hpack(res[kc][1].x, res[kc][1].y);
                xa[kc][2] = hpack(res[kc][2].x, res[kc][2].y);
                xa[kc][3] = hpack(res[kc][3].x, res[kc][3].y);
            }
        }

        // ---- matmul1: 16 rows x 64 hidden, one mma per (nt, kc) ----
        float c1[8][4];
        {
            const u64* b1q = (const u64*)(B1p[layer] + blk * 64);
            #pragma unroll
            for (int nt = 0; nt < 8; ++nt) {
                float blo, bhi;
                unpack2(b1q[nt * 4 + t4], blo, bhi);
                c1[nt][0] = blo; c1[nt][1] = bhi; c1[nt][2] = blo; c1[nt][3] = bhi;
            }
        }
        #pragma unroll
        for (int nt = 0; nt < 8; ++nt) {
            uint4 B = w1q[nt * 32];            // cells 2nt (kc=0), 2nt+1 (kc=1)
            mma16(c1[nt], xa[0], B.x, B.y);
            mma16(c1[nt], xa[1], B.z, B.w);
        }

        // ---- ELU in registers, rebuild mm2 A-fragments directly ----
        u32 a2[4][4];
        #pragma unroll
        for (int nt = 0; nt < 8; ++nt) {
            c1[nt][0] = elu(c1[nt][0]); c1[nt][1] = elu(c1[nt][1]);
            c1[nt][2] = elu(c1[nt][2]); c1[nt][3] = elu(c1[nt][3]);
        }
        #pragma unroll
        for (int kt = 0; kt < 4; ++kt) {
            a2[kt][0] = hpack(c1[2*kt][0],   c1[2*kt][1]);
            a2[kt][1] = hpack(c1[2*kt][2],   c1[2*kt][3]);
            a2[kt][2] = hpack(c1[2*kt+1][0], c1[2*kt+1][1]);
            a2[kt][3] = hpack(c1[2*kt+1][2], c1[2*kt+1][3]);
        }

        // ---- matmul2: 16 rows x 32 out; bias + residual from registers ----
        float c2[4][4];
        {
            const u64* b2q = (const u64*)(B2p[layer] + blk * 32);
            #pragma unroll
            for (int nt = 0; nt < 4; ++nt) {
                float blo, bhi;
                unpack2(b2q[nt * 4 + t4], blo, bhi);
                const float2 rl = res[nt >> 1][(nt & 1) * 2];      // row g
                const float2 rh = res[nt >> 1][(nt & 1) * 2 + 1];  // row g+8
                c2[nt][0] = blo + rl.x; c2[nt][1] = bhi + rl.y;
                c2[nt][2] = blo + rh.x; c2[nt][3] = bhi + rh.y;
            }
        }
        #pragma unroll
        for (int nt = 0; nt < 4; ++nt) {
            uint4 B01 = w2q[(nt * 2 + 0) * 32];   // cells nt*4+0, nt*4+1 (kt 0,1)
            uint4 B23 = w2q[(nt * 2 + 1) * 32];   // cells nt*4+2, nt*4+3 (kt 2,3)
            mma16(c2[nt], a2[0], B01.x, B01.y);
            mma16(c2[nt], a2[1], B01.z, B01.w);
            mma16(c2[nt], a2[2], B23.x, B23.y);
            mma16(c2[nt], a2[3], B23.z, B23.w);
        }

        // ---- writeback ----
        {
            float* resp = tile + g * TS + cbase;
            #pragma unroll
            for (int nt = 0; nt < 4; ++nt) {
                *(u64*)(resp + nt * 8 + 2 * t4)          = pack2(c2[nt][0], c2[nt][1]);
                *(u64*)(resp + 8 * TS + nt * 8 + 2 * t4) = pack2(c2[nt][2], c2[nt][3]);
            }
        }
    }

    __syncthreads();
    transpose_tile(tile, warp, lane);        // undo layer-1 permutation
    __syncthreads();

    // ---- store output ----
    {
        float4* dst = (float4*)(out + row0 * 1024);
        #pragma unroll
        for (int it = 0; it < 16; ++it) {
            int i = tid + it * NTHREADS;
            int r = i >> 8, c4 = i & 255;
            dst[r * 256 + c4] = *(const float4*)(tile + r * TS + c4 * 4);
        }
    }
}

extern "C" void kernel_launch(void* const* d_in, const int* in_sizes, int n_in,
                              void* d_out, int out_size) {
    const float* x   = (const float*)d_in[0];
    const float* W1a = (const float*)d_in[1];
    const float* B1a = (const float*)d_in[2];
    const float* W2a = (const float*)d_in[3];
    const float* B2a = (const float*)d_in[4];
    const float* W1b = (const float*)d_in[5];
    const float* B1b = (const float*)d_in[6];
    const float* W2b = (const float*)d_in[7];
    const float* B2b = (const float*)d_in[8];
    float* out = (float*)d_out;

    int rows = in_sizes[0] / 1024;
    int grid = rows / ROWS;                    // 1024

    size_t smem_bytes = (size_t)SM_TOTAL * sizeof(float);   // 65792 B
    static int configured = -1;
    if (configured < 0) {
        cudaFuncSetAttribute(mixer_kernel,
                             cudaFuncAttributeMaxDynamicSharedMemorySize,
                             (int)smem_bytes);
        configured = 1;
    }

    prep_kernel<<<256, 256>>>(W1a, W2a, W1b, W2b);
    mixer_kernel<<<grid, NTHREADS, smem_bytes>>>(
        x, B1a, B2a, B1b, B2b, out);
}